// round 1
// baseline (speedup 1.0000x reference)
#include <cuda_runtime.h>
#include <math.h>

#define Nn 16384
#define Dd 128
#define Cc 10
#define Kk 16
#define EPSf 1.1920928955078125e-7f
#define LOG2PIf 1.8378770664093453f
#define LN2f 0.6931471805599453f

// scratch (static __device__ arrays; no allocation)
__device__ float  g_inv[Cc * Kk * Dd];
__device__ float  g_m2 [Cc * Kk * Dd];
__device__ float  g_pre[Cc * Kk];
__device__ float  g_base[Cc * Kk];
__device__ double g_sum[Cc];
__device__ int    g_cnt[Cc];

__device__ __forceinline__ float softplusf(float x) {
    // matches jax.nn.softplus = logaddexp(x, 0)
    return fmaxf(x, 0.0f) + log1pf(expf(-fabsf(x)));
}

// ---------------- Kernel A1: per-(c,k) precompute -----------------
// one warp per (c,k); lane l owns d = 4l..4l+3 (float4)
__global__ void prep_kernel(const float* __restrict__ mu,
                            const float* __restrict__ lower,
                            const float* __restrict__ upper,
                            const float* __restrict__ sigma) {
    int w    = (blockIdx.x * blockDim.x + threadIdx.x) >> 5;
    int lane = threadIdx.x & 31;
    if (w >= Cc * Kk) return;
    int base = w * Dd + lane * 4;

    float4 m4 = *(const float4*)(mu    + base);
    float4 l4 = *(const float4*)(lower + base);
    float4 u4 = *(const float4*)(upper + base);
    float4 s4 = *(const float4*)(sigma + base);

    float mv[4] = {m4.x, m4.y, m4.z, m4.w};
    float lv[4] = {l4.x, l4.y, l4.z, l4.w};
    float uv[4] = {u4.x, u4.y, u4.z, u4.w};
    float sv[4] = {s4.x, s4.y, s4.z, s4.w};

    float invv[4], m2v[4];
    float prod = 1.0f, slog = 0.0f;
#pragma unroll
    for (int j = 0; j < 4; j++) {
        float scale = EPSf + softplusf(sv[j]);
        float inv   = 1.0f / scale;
        float z = normcdff((uv[j] - mv[j]) * inv) - normcdff((lv[j] - mv[j]) * inv);
        prod *= z;
        slog += logf(scale);
        invv[j] = inv;
        m2v[j]  = mv[j] * inv;
    }
    *(float4*)(g_inv + base) = make_float4(invv[0], invv[1], invv[2], invv[3]);
    *(float4*)(g_m2  + base) = make_float4(m2v[0],  m2v[1],  m2v[2],  m2v[3]);

#pragma unroll
    for (int o = 16; o > 0; o >>= 1) {
        prod *= __shfl_xor_sync(0xffffffffu, prod, o);
        slog += __shfl_xor_sync(0xffffffffu, slog, o);
    }
    if (lane == 0)
        g_pre[w] = -logf(prod + EPSf) - slog;   // -log_norm - sum(log scale)
}

// ---------------- Kernel A2: base + zero accumulators -----------------
// 160 threads = 5 warps; width-16 shfl groups = one class each
__global__ void base_kernel(const float* __restrict__ logits_k,
                            const float* __restrict__ eta_p) {
    int t = threadIdx.x;
    if (t < Cc) { g_sum[t] = 0.0; g_cnt[t] = 0; }
    if (t < Cc * Kk) {
        float lg = logits_k[t];
        float m = lg;
#pragma unroll
        for (int o = 8; o > 0; o >>= 1)
            m = fmaxf(m, __shfl_xor_sync(0xffffffffu, m, o, 16));
        float e = expf(lg - m);
        float se = e;
#pragma unroll
        for (int o = 8; o > 0; o >>= 1)
            se += __shfl_xor_sync(0xffffffffu, se, o, 16);
        float log_cat = lg - (m + logf(se));
        float eta = *eta_p;
        float etac = (eta == 0.0f) ? (-2.0f * Dd * LN2f) : 0.0f;
        g_base[t] = log_cat + g_pre[t] - 0.5f * Dd * LOG2PIf + etac;
    }
}

// ---------------- Kernel B: main per-row work -----------------
__global__ void __launch_bounds__(256)
main_kernel(const float* __restrict__ X, const int* __restrict__ y,
            const float* __restrict__ resp,
            const float* __restrict__ lower, const float* __restrict__ upper,
            const float* __restrict__ eta_p) {
    __shared__ float ssum[Cc];
    __shared__ int   scnt[Cc];
    int t = threadIdx.x;
    if (t < Cc) { ssum[t] = 0.0f; scnt[t] = 0; }
    __syncthreads();

    int lane = t & 31;
    int gw   = blockIdx.x * (blockDim.x >> 5) + (t >> 5);
    int nw   = gridDim.x * (blockDim.x >> 5);
    float eta = *eta_p;

    for (int n = gw; n < Nn; n += nw) {
        int c = __ldg(y + n);
        float4 xv = *(const float4*)(X + (size_t)n * Dd + lane * 4);

        float respl = 0.0f, tl = 0.0f;
        if (lane < Kk) {
            respl = __ldg(resp + ((size_t)c * Nn + n) * Kk + lane);
            tl = respl * g_base[c * Kk + lane];
        }

        const float4* ip = (const float4*)g_inv + (size_t)c * Kk * (Dd / 4) + lane;
        const float4* mp = (const float4*)g_m2  + (size_t)c * Kk * (Dd / 4) + lane;

        if (eta == 0.0f) {
#pragma unroll 4
            for (int k = 0; k < Kk; k++) {
                float4 iv = ip[k * (Dd / 4)];
                float4 mv = mp[k * (Dd / 4)];
                float z0 = fmaf(xv.x, iv.x, -mv.x);
                float z1 = fmaf(xv.y, iv.y, -mv.y);
                float z2 = fmaf(xv.z, iv.z, -mv.z);
                float z3 = fmaf(xv.w, iv.w, -mv.w);
                float s  = fmaf(z0, z0, fmaf(z1, z1, fmaf(z2, z2, z3 * z3)));
                float r  = __shfl_sync(0xffffffffu, respl, k);
                tl = fmaf(-0.5f * r, s, tl);
            }
        } else {
            const float4* lp = (const float4*)lower + (size_t)c * Kk * (Dd / 4) + lane;
            const float4* up = (const float4*)upper + (size_t)c * Kk * (Dd / 4) + lane;
#pragma unroll 2
            for (int k = 0; k < Kk; k++) {
                float4 iv = ip[k * (Dd / 4)];
                float4 mv = mp[k * (Dd / 4)];
                float4 lo = lp[k * (Dd / 4)];
                float4 uu = up[k * (Dd / 4)];
                float z0 = fmaf(xv.x, iv.x, -mv.x);
                float z1 = fmaf(xv.y, iv.y, -mv.y);
                float z2 = fmaf(xv.z, iv.z, -mv.z);
                float z3 = fmaf(xv.w, iv.w, -mv.w);
                float s  = fmaf(z0, z0, fmaf(z1, z1, fmaf(z2, z2, z3 * z3)));
                float q  = softplusf(-eta * (xv.x - lo.x)) + softplusf(-eta * (uu.x - xv.x))
                         + softplusf(-eta * (xv.y - lo.y)) + softplusf(-eta * (uu.y - xv.y))
                         + softplusf(-eta * (xv.z - lo.z)) + softplusf(-eta * (uu.z - xv.z))
                         + softplusf(-eta * (xv.w - lo.w)) + softplusf(-eta * (uu.w - xv.w));
                float r  = __shfl_sync(0xffffffffu, respl, k);
                tl -= r * (fmaf(0.5f, s, q));
            }
        }

#pragma unroll
        for (int o = 16; o > 0; o >>= 1)
            tl += __shfl_xor_sync(0xffffffffu, tl, o);
        if (lane == 0) {
            atomicAdd(&ssum[c], tl);
            atomicAdd(&scnt[c], 1);
        }
    }

    __syncthreads();
    if (t < Cc) {
        if (scnt[t] > 0) {
            atomicAdd(&g_sum[t], (double)ssum[t]);
            atomicAdd(&g_cnt[t], scnt[t]);
        }
    }
}

// ---------------- Kernel C: final reduce -----------------
__global__ void reduce_kernel(float* __restrict__ out) {
    int t = threadIdx.x;
    double v = 0.0;
    if (t < Cc) {
        int cn = g_cnt[t];
        if (cn > 0) v = g_sum[t] / ((double)cn * (double)Kk);
    }
#pragma unroll
    for (int o = 16; o > 0; o >>= 1)
        v += __shfl_xor_sync(0xffffffffu, v, o);
    if (t == 0) out[0] = (float)(-v);
}

extern "C" void kernel_launch(void* const* d_in, const int* in_sizes, int n_in,
                              void* d_out, int out_size) {
    const float* X      = (const float*)d_in[0];
    const int*   y      = (const int*)  d_in[1];
    const float* resp   = (const float*)d_in[2];
    const float* mu     = (const float*)d_in[3];
    const float* lower  = (const float*)d_in[4];
    const float* upper  = (const float*)d_in[5];
    const float* sigma  = (const float*)d_in[6];
    const float* logits = (const float*)d_in[7];
    const float* eta    = (const float*)d_in[8];
    float* out = (float*)d_out;

    prep_kernel<<<40, 128>>>(mu, lower, upper, sigma);
    base_kernel<<<1, 160>>>(logits, eta);
    main_kernel<<<512, 256>>>(X, y, resp, lower, upper, eta);
    reduce_kernel<<<1, 32>>>(out);
}

// round 2
// speedup vs baseline: 1.2059x; 1.2059x over previous
#include <cuda_runtime.h>
#include <math.h>

#define Nn 16384
#define Dd 128
#define Cc 10
#define Kk 16
#define EPSf 1.1920928955078125e-7f
#define LOG2PIf 1.8378770664093453f
#define LN2f 0.6931471805599453f

// static scratch (no allocation)
__device__ float    g_inv[Cc * Kk * Dd];
__device__ float    g_m2 [Cc * Kk * Dd];
__device__ float    g_pre[Cc * Kk];
__device__ float    g_sum[Cc];
__device__ int      g_cnt[Cc];
__device__ int      g_rows[Cc * Nn];
__device__ unsigned g_done;

__device__ __forceinline__ float softplusf(float x) {
    return fmaxf(x, 0.0f) + log1pf(expf(-fabsf(x)));
}

// ---------------- Kernel 1: per-(c,k) precompute + accumulator reset ----------
// one warp per (c,k); lane l owns d = 4l..4l+3
__global__ void prep_kernel(const float* __restrict__ mu,
                            const float* __restrict__ lower,
                            const float* __restrict__ upper,
                            const float* __restrict__ sigma) {
    if (blockIdx.x == 0) {
        int t = threadIdx.x;
        if (t < Cc) { g_sum[t] = 0.0f; g_cnt[t] = 0; }
        if (t == 0) g_done = 0u;
    }
    int w    = (blockIdx.x * blockDim.x + threadIdx.x) >> 5;
    int lane = threadIdx.x & 31;
    if (w >= Cc * Kk) return;
    int base = w * Dd + lane * 4;

    float4 m4 = *(const float4*)(mu    + base);
    float4 l4 = *(const float4*)(lower + base);
    float4 u4 = *(const float4*)(upper + base);
    float4 s4 = *(const float4*)(sigma + base);

    float mv[4] = {m4.x, m4.y, m4.z, m4.w};
    float lv[4] = {l4.x, l4.y, l4.z, l4.w};
    float uv[4] = {u4.x, u4.y, u4.z, u4.w};
    float sv[4] = {s4.x, s4.y, s4.z, s4.w};

    float invv[4], m2v[4];
    float prod = 1.0f, slog = 0.0f;
#pragma unroll
    for (int j = 0; j < 4; j++) {
        float scale = EPSf + softplusf(sv[j]);
        float inv   = 1.0f / scale;
        float z = normcdff((uv[j] - mv[j]) * inv) - normcdff((lv[j] - mv[j]) * inv);
        prod *= z;
        slog += logf(scale);
        invv[j] = inv;
        m2v[j]  = mv[j] * inv;
    }
    *(float4*)(g_inv + base) = make_float4(invv[0], invv[1], invv[2], invv[3]);
    *(float4*)(g_m2  + base) = make_float4(m2v[0],  m2v[1],  m2v[2],  m2v[3]);

#pragma unroll
    for (int o = 16; o > 0; o >>= 1) {
        prod *= __shfl_xor_sync(0xffffffffu, prod, o);
        slog += __shfl_xor_sync(0xffffffffu, slog, o);
    }
    if (lane == 0)
        g_pre[w] = -logf(prod + EPSf) - slog;   // -log_norm - sum(log scale)
}

// ---------------- Kernel 2: bucket rows by class -----------------------------
// 64 blocks x 256 threads = exactly N rows
__global__ void bucket_kernel(const int* __restrict__ y) {
    __shared__ int s_cnt[Cc];
    __shared__ int s_off[Cc];
    int t = threadIdx.x;
    if (t < Cc) s_cnt[t] = 0;
    __syncthreads();
    int n = blockIdx.x * blockDim.x + t;
    int c = y[n];
    atomicAdd(&s_cnt[c], 1);
    __syncthreads();
    if (t < Cc) {
        s_off[t] = atomicAdd(&g_cnt[t], s_cnt[t]);
        s_cnt[t] = 0;
    }
    __syncthreads();
    int pos = atomicAdd(&s_cnt[c], 1);
    g_rows[c * Nn + s_off[c] + pos] = n;
}

// ---------------- Kernel 3: fused base + register-GEMM main + reduce ---------
// grid 145 x 256: 1160 warps, each warp owns class c = w%10, slice s = w/10
__global__ void __launch_bounds__(256, 1)
main_kernel(const float* __restrict__ X, const int* __restrict__ y,
            const float* __restrict__ resp,
            const float* __restrict__ lower, const float* __restrict__ upper,
            const float* __restrict__ logits_k,
            const float* __restrict__ eta_p,
            float* __restrict__ out) {
    __shared__ float s_base[Cc * Kk];
    __shared__ bool  s_last;
    int t = threadIdx.x;
    float eta = *eta_p;

    // per-block base[c,k] = log_cat + g_pre - D/2*log2pi (+ eta==0 shortcut)
    if (t < Cc * Kk) {
        float lg = logits_k[t];
        float m = lg;
#pragma unroll
        for (int o = 8; o > 0; o >>= 1)
            m = fmaxf(m, __shfl_xor_sync(0xffffffffu, m, o, 16));
        float e = expf(lg - m);
        float se = e;
#pragma unroll
        for (int o = 8; o > 0; o >>= 1)
            se += __shfl_xor_sync(0xffffffffu, se, o, 16);
        float log_cat = lg - (m + logf(se));
        float etac = (eta == 0.0f) ? (-2.0f * Dd * LN2f) : 0.0f;
        s_base[t] = log_cat + g_pre[t] - 0.5f * Dd * LOG2PIf + etac;
    }
    __syncthreads();

    int lane = t & 31;
    int w    = blockIdx.x * (blockDim.x >> 5) + (t >> 5);
    int c    = w % Cc;
    int s    = w / Cc;
    int S    = gridDim.x * (blockDim.x >> 5) / Cc;
    int cnt  = g_cnt[c];

    // load this class's weights into registers: 128 floats/lane
    float4 IV[Kk], MV[Kk];
    {
        const float4* gi = (const float4*)g_inv + (size_t)c * Kk * (Dd / 4) + lane;
        const float4* gm = (const float4*)g_m2  + (size_t)c * Kk * (Dd / 4) + lane;
#pragma unroll
        for (int k = 0; k < Kk; k++) IV[k] = gi[k * (Dd / 4)];
#pragma unroll
        for (int k = 0; k < Kk; k++) MV[k] = gm[k * (Dd / 4)];
    }

    const int* rowlist = g_rows + (size_t)c * Nn;
    float acc = 0.0f;

    int pos = s;
    int n_nx = 0; float4 x_nx = make_float4(0.f,0.f,0.f,0.f); float r_nx = 0.0f;
    if (pos < cnt) {
        n_nx = rowlist[pos];
        x_nx = *(const float4*)(X + (size_t)n_nx * Dd + lane * 4);
        if (lane < Kk) r_nx = __ldg(resp + ((size_t)c * Nn + n_nx) * Kk + lane);
    }

    if (eta == 0.0f) {
        for (; pos < cnt; pos += S) {
            int n = n_nx; float4 xv = x_nx; float respl = r_nx;
            int p2 = pos + S;
            if (p2 < cnt) {
                n_nx = rowlist[p2];
                x_nx = *(const float4*)(X + (size_t)n_nx * Dd + lane * 4);
                if (lane < Kk) r_nx = __ldg(resp + ((size_t)c * Nn + n_nx) * Kk + lane);
            }
            float tl = (lane < Kk) ? respl * s_base[c * Kk + lane] : 0.0f;
#pragma unroll
            for (int k = 0; k < Kk; k++) {
                float z0 = fmaf(xv.x, IV[k].x, -MV[k].x);
                float z1 = fmaf(xv.y, IV[k].y, -MV[k].y);
                float z2 = fmaf(xv.z, IV[k].z, -MV[k].z);
                float z3 = fmaf(xv.w, IV[k].w, -MV[k].w);
                float sq = fmaf(z0, z0, fmaf(z1, z1, fmaf(z2, z2, z3 * z3)));
                float r  = __shfl_sync(0xffffffffu, respl, k);
                tl = fmaf(-0.5f * r, sq, tl);
            }
            acc += tl;
        }
    } else {
        // general path (eta != 0): adds the two softplus barrier terms
        for (; pos < cnt; pos += S) {
            int n = n_nx; float4 xv = x_nx; float respl = r_nx;
            int p2 = pos + S;
            if (p2 < cnt) {
                n_nx = rowlist[p2];
                x_nx = *(const float4*)(X + (size_t)n_nx * Dd + lane * 4);
                if (lane < Kk) r_nx = __ldg(resp + ((size_t)c * Nn + n_nx) * Kk + lane);
            }
            float tl = (lane < Kk) ? respl * s_base[c * Kk + lane] : 0.0f;
            const float4* lp = (const float4*)lower + (size_t)c * Kk * (Dd / 4) + lane;
            const float4* up = (const float4*)upper + (size_t)c * Kk * (Dd / 4) + lane;
#pragma unroll
            for (int k = 0; k < Kk; k++) {
                float4 lo = lp[k * (Dd / 4)];
                float4 uu = up[k * (Dd / 4)];
                float z0 = fmaf(xv.x, IV[k].x, -MV[k].x);
                float z1 = fmaf(xv.y, IV[k].y, -MV[k].y);
                float z2 = fmaf(xv.z, IV[k].z, -MV[k].z);
                float z3 = fmaf(xv.w, IV[k].w, -MV[k].w);
                float sq = fmaf(z0, z0, fmaf(z1, z1, fmaf(z2, z2, z3 * z3)));
                float q  = softplusf(-eta * (xv.x - lo.x)) + softplusf(-eta * (uu.x - xv.x))
                         + softplusf(-eta * (xv.y - lo.y)) + softplusf(-eta * (uu.y - xv.y))
                         + softplusf(-eta * (xv.z - lo.z)) + softplusf(-eta * (uu.z - xv.z))
                         + softplusf(-eta * (xv.w - lo.w)) + softplusf(-eta * (uu.w - xv.w));
                float r  = __shfl_sync(0xffffffffu, respl, k);
                tl -= r * fmaf(0.5f, sq, q);
            }
            acc += tl;
        }
    }

    // warp reduce, one atomic per warp
#pragma unroll
    for (int o = 16; o > 0; o >>= 1)
        acc += __shfl_xor_sync(0xffffffffu, acc, o);
    if (lane == 0) atomicAdd(&g_sum[c], acc);

    // last-block final reduction
    __threadfence();
    __syncthreads();
    if (t == 0) {
        unsigned d = atomicAdd(&g_done, 1u);
        s_last = (d == gridDim.x - 1);
    }
    __syncthreads();
    if (s_last && t < 32) {
        double v = 0.0;
        if (t < Cc) {
            int cn = g_cnt[t];
            if (cn > 0) v = (double)g_sum[t] / ((double)cn * (double)Kk);
        }
#pragma unroll
        for (int o = 16; o > 0; o >>= 1)
            v += __shfl_xor_sync(0xffffffffu, v, o);
        if (t == 0) out[0] = (float)(-v);
    }
}

extern "C" void kernel_launch(void* const* d_in, const int* in_sizes, int n_in,
                              void* d_out, int out_size) {
    const float* X      = (const float*)d_in[0];
    const int*   y      = (const int*)  d_in[1];
    const float* resp   = (const float*)d_in[2];
    const float* mu     = (const float*)d_in[3];
    const float* lower  = (const float*)d_in[4];
    const float* upper  = (const float*)d_in[5];
    const float* sigma  = (const float*)d_in[6];
    const float* logits = (const float*)d_in[7];
    const float* eta    = (const float*)d_in[8];
    float* out = (float*)d_out;

    prep_kernel<<<40, 128>>>(mu, lower, upper, sigma);
    bucket_kernel<<<Nn / 256, 256>>>(y);
    main_kernel<<<145, 256>>>(X, y, resp, lower, upper, logits, eta, out);
}

// round 3
// speedup vs baseline: 1.2097x; 1.0031x over previous
#include <cuda_runtime.h>
#include <math.h>

#define Nn 16384
#define Dd 128
#define Cc 10
#define Kk 16
#define NB 145
#define EPSf 1.1920928955078125e-7f
#define LOG2PIf 1.8378770664093453f
#define LN2f 0.6931471805599453f

// static scratch (no allocation); all-zero initial state, restored at end of
// every run by the winner block so graph replays are self-contained.
__device__ float    g_inv[Cc * Kk * Dd];
__device__ float    g_m2 [Cc * Kk * Dd];
__device__ float    g_pre[Cc * Kk];
__device__ float    g_sum[Cc];
__device__ int      g_cnt[Cc];
__device__ int      g_rows[Cc * Nn];
__device__ unsigned g_bar;
__device__ unsigned g_done;

__device__ __forceinline__ float softplusf(float x) {
    return fmaxf(x, 0.0f) + log1pf(expf(-fabsf(x)));
}

__global__ void __launch_bounds__(256, 1)
fused_kernel(const float* __restrict__ X, const int* __restrict__ y,
             const float* __restrict__ resp,
             const float* __restrict__ mu,
             const float* __restrict__ lower, const float* __restrict__ upper,
             const float* __restrict__ sigma,
             const float* __restrict__ logits_k,
             const float* __restrict__ eta_p,
             float* __restrict__ out) {
    __shared__ int   s_cnt[Cc];
    __shared__ int   s_off[Cc];
    __shared__ float s_base[Cc * Kk];
    __shared__ bool  s_last;

    int t    = threadIdx.x;
    int lane = t & 31;
    float eta = *eta_p;

    // ---------------- Phase A1: bucket rows by class (blocks 0..63) ----------
    int n0 = blockIdx.x * blockDim.x + t;
    int c_row = -1;
    if (t < Cc) s_cnt[t] = 0;
    __syncthreads();
    if (n0 < Nn) { c_row = y[n0]; atomicAdd(&s_cnt[c_row], 1); }
    __syncthreads();
    if (t < Cc) { s_off[t] = atomicAdd(&g_cnt[t], s_cnt[t]); s_cnt[t] = 0; }
    __syncthreads();
    if (n0 < Nn) {
        int p = atomicAdd(&s_cnt[c_row], 1);
        g_rows[c_row * Nn + s_off[c_row] + p] = n0;
    }

    // ---------------- Phase A2: per-(c,k) precompute (warps 0..159) ----------
    int w = blockIdx.x * (blockDim.x >> 5) + (t >> 5);
    if (w < Cc * Kk) {
        int base = w * Dd + lane * 4;
        float4 m4 = *(const float4*)(mu    + base);
        float4 l4 = *(const float4*)(lower + base);
        float4 u4 = *(const float4*)(upper + base);
        float4 s4 = *(const float4*)(sigma + base);
        float mv[4] = {m4.x, m4.y, m4.z, m4.w};
        float lv[4] = {l4.x, l4.y, l4.z, l4.w};
        float uv[4] = {u4.x, u4.y, u4.z, u4.w};
        float sv[4] = {s4.x, s4.y, s4.z, s4.w};
        float invv[4], m2v[4];
        float prod = 1.0f, slog = 0.0f;
#pragma unroll
        for (int j = 0; j < 4; j++) {
            float scale = EPSf + softplusf(sv[j]);
            float inv   = 1.0f / scale;
            float z = normcdff((uv[j] - mv[j]) * inv) - normcdff((lv[j] - mv[j]) * inv);
            prod *= z;
            slog += logf(scale);
            invv[j] = inv;
            m2v[j]  = mv[j] * inv;
        }
        *(float4*)(g_inv + base) = make_float4(invv[0], invv[1], invv[2], invv[3]);
        *(float4*)(g_m2  + base) = make_float4(m2v[0],  m2v[1],  m2v[2],  m2v[3]);
#pragma unroll
        for (int o = 16; o > 0; o >>= 1) {
            prod *= __shfl_xor_sync(0xffffffffu, prod, o);
            slog += __shfl_xor_sync(0xffffffffu, slog, o);
        }
        if (lane == 0)
            g_pre[w] = -logf(prod + EPSf) - slog;  // -log_norm - sum(log scale)
    }

    // ---------------- grid barrier (all 145 blocks co-resident) --------------
    __syncthreads();
    if (t == 0) {
        __threadfence();
        atomicAdd(&g_bar, 1u);
        while (*(volatile unsigned*)&g_bar < (unsigned)NB) { }
        __threadfence();
    }
    __syncthreads();

    // ---------------- base[c,k] into smem (per block) ------------------------
    if (t < Cc * Kk) {
        float lg = logits_k[t];
        float m = lg;
#pragma unroll
        for (int o = 8; o > 0; o >>= 1)
            m = fmaxf(m, __shfl_xor_sync(0xffffffffu, m, o, 16));
        float e = expf(lg - m);
        float se = e;
#pragma unroll
        for (int o = 8; o > 0; o >>= 1)
            se += __shfl_xor_sync(0xffffffffu, se, o, 16);
        float log_cat = lg - (m + logf(se));
        float etac = (eta == 0.0f) ? (-2.0f * Dd * LN2f) : 0.0f;
        s_base[t] = log_cat + g_pre[t] - 0.5f * Dd * LOG2PIf + etac;
    }
    __syncthreads();

    // ---------------- Phase B: register-resident main loop --------------------
    int c   = w % Cc;
    int s   = w / Cc;
    int S   = (NB * 8) / Cc;            // 116 slices per class
    int cnt = g_cnt[c];

    float4 IV[Kk], MV[Kk];
    {
        const float4* gi = (const float4*)g_inv + (size_t)c * Kk * (Dd / 4) + lane;
        const float4* gm = (const float4*)g_m2  + (size_t)c * Kk * (Dd / 4) + lane;
#pragma unroll
        for (int k = 0; k < Kk; k++) IV[k] = gi[k * (Dd / 4)];
#pragma unroll
        for (int k = 0; k < Kk; k++) MV[k] = gm[k * (Dd / 4)];
    }

    const int* rowlist = g_rows + (size_t)c * Nn;
    float acc = 0.0f;

    int pos = s;
    int n_nx = 0; float4 x_nx = make_float4(0.f, 0.f, 0.f, 0.f); float r_nx = 0.0f;
    if (pos < cnt) {
        n_nx = rowlist[pos];
        x_nx = *(const float4*)(X + (size_t)n_nx * Dd + lane * 4);
        if (lane < Kk) r_nx = __ldg(resp + ((size_t)c * Nn + n_nx) * Kk + lane);
    }

    if (eta == 0.0f) {
        for (; pos < cnt; pos += S) {
            float4 xv = x_nx; float respl = r_nx;
            int p2 = pos + S;
            if (p2 < cnt) {
                n_nx = rowlist[p2];
                x_nx = *(const float4*)(X + (size_t)n_nx * Dd + lane * 4);
                if (lane < Kk) r_nx = __ldg(resp + ((size_t)c * Nn + n_nx) * Kk + lane);
            }
            float tl = (lane < Kk) ? respl * s_base[c * Kk + lane] : 0.0f;
#pragma unroll
            for (int k = 0; k < Kk; k++) {
                float z0 = fmaf(xv.x, IV[k].x, -MV[k].x);
                float z1 = fmaf(xv.y, IV[k].y, -MV[k].y);
                float z2 = fmaf(xv.z, IV[k].z, -MV[k].z);
                float z3 = fmaf(xv.w, IV[k].w, -MV[k].w);
                float sq = fmaf(z0, z0, fmaf(z1, z1, fmaf(z2, z2, z3 * z3)));
                float r  = __shfl_sync(0xffffffffu, respl, k);
                tl = fmaf(-0.5f * r, sq, tl);
            }
            acc += tl;
        }
    } else {
        for (; pos < cnt; pos += S) {
            float4 xv = x_nx; float respl = r_nx;
            int p2 = pos + S;
            if (p2 < cnt) {
                n_nx = rowlist[p2];
                x_nx = *(const float4*)(X + (size_t)n_nx * Dd + lane * 4);
                if (lane < Kk) r_nx = __ldg(resp + ((size_t)c * Nn + n_nx) * Kk + lane);
            }
            float tl = (lane < Kk) ? respl * s_base[c * Kk + lane] : 0.0f;
            const float4* lp = (const float4*)lower + (size_t)c * Kk * (Dd / 4) + lane;
            const float4* up = (const float4*)upper + (size_t)c * Kk * (Dd / 4) + lane;
#pragma unroll
            for (int k = 0; k < Kk; k++) {
                float4 lo = lp[k * (Dd / 4)];
                float4 uu = up[k * (Dd / 4)];
                float z0 = fmaf(xv.x, IV[k].x, -MV[k].x);
                float z1 = fmaf(xv.y, IV[k].y, -MV[k].y);
                float z2 = fmaf(xv.z, IV[k].z, -MV[k].z);
                float z3 = fmaf(xv.w, IV[k].w, -MV[k].w);
                float sq = fmaf(z0, z0, fmaf(z1, z1, fmaf(z2, z2, z3 * z3)));
                float q  = softplusf(-eta * (xv.x - lo.x)) + softplusf(-eta * (uu.x - xv.x))
                         + softplusf(-eta * (xv.y - lo.y)) + softplusf(-eta * (uu.y - xv.y))
                         + softplusf(-eta * (xv.z - lo.z)) + softplusf(-eta * (uu.z - xv.z))
                         + softplusf(-eta * (xv.w - lo.w)) + softplusf(-eta * (uu.w - xv.w));
                float r  = __shfl_sync(0xffffffffu, respl, k);
                tl -= r * fmaf(0.5f, sq, q);
            }
            acc += tl;
        }
    }

#pragma unroll
    for (int o = 16; o > 0; o >>= 1)
        acc += __shfl_xor_sync(0xffffffffu, acc, o);
    if (lane == 0) atomicAdd(&g_sum[c], acc);

    // ---------------- last block: final reduce + state reset ------------------
    __threadfence();
    __syncthreads();
    if (t == 0) {
        unsigned d = atomicAdd(&g_done, 1u);
        s_last = (d == (unsigned)(NB - 1));
    }
    __syncthreads();
    if (s_last && t < 32) {
        double v = 0.0;
        int cn = 0;
        if (t < Cc) {
            cn = g_cnt[t];
            if (cn > 0) v = (double)g_sum[t] / ((double)cn * (double)Kk);
        }
#pragma unroll
        for (int o = 16; o > 0; o >>= 1)
            v += __shfl_xor_sync(0xffffffffu, v, o);
        if (t == 0) out[0] = (float)(-v);
        // reset state for next graph replay
        if (t < Cc) { g_sum[t] = 0.0f; g_cnt[t] = 0; }
        if (t == 0) { g_bar = 0u; g_done = 0u; }
    }
}

extern "C" void kernel_launch(void* const* d_in, const int* in_sizes, int n_in,
                              void* d_out, int out_size) {
    const float* X      = (const float*)d_in[0];
    const int*   y      = (const int*)  d_in[1];
    const float* resp   = (const float*)d_in[2];
    const float* mu     = (const float*)d_in[3];
    const float* lower  = (const float*)d_in[4];
    const float* upper  = (const float*)d_in[5];
    const float* sigma  = (const float*)d_in[6];
    const float* logits = (const float*)d_in[7];
    const float* eta    = (const float*)d_in[8];
    float* out = (float*)d_out;

    fused_kernel<<<NB, 256>>>(X, y, resp, mu, lower, upper, sigma, logits, eta, out);
}

// round 4
// speedup vs baseline: 1.3397x; 1.1075x over previous
#include <cuda_runtime.h>
#include <math.h>

#define Nn 16384
#define Dd 128
#define Cc 10
#define Kk 16
#define NB 145
#define EPSf 1.1920928955078125e-7f
#define LOG2PIf 1.8378770664093453f
#define LN2f 0.6931471805599453f

// static scratch (no allocation); all-zero initial state, restored at end of
// every run by the winner block so graph replays are self-contained.
__device__ float    g_inv[Cc * Kk * Dd];
__device__ float    g_m2 [Cc * Kk * Dd];
__device__ float    g_pre[Cc * Kk];
__device__ float    g_sum[Cc];
__device__ int      g_cnt[Cc];
__device__ int      g_rows[Cc * Nn];
__device__ unsigned g_bar;
__device__ unsigned g_done;

__device__ __forceinline__ float softplusf(float x) {
    return fmaxf(x, 0.0f) + log1pf(expf(-fabsf(x)));
}

__global__ void __launch_bounds__(256, 1)
fused_kernel(const float* __restrict__ X, const int* __restrict__ y,
             const float* __restrict__ resp,
             const float* __restrict__ mu,
             const float* __restrict__ lower, const float* __restrict__ upper,
             const float* __restrict__ sigma,
             const float* __restrict__ logits_k,
             const float* __restrict__ eta_p,
             float* __restrict__ out) {
    __shared__ int   s_cnt[Cc];
    __shared__ int   s_off[Cc];
    __shared__ float s_base2[Cc * Kk];   // = -2 * base  (for the eta==0 fast path)
    __shared__ bool  s_last;

    int t    = threadIdx.x;
    int lane = t & 31;
    float eta = *eta_p;

    // ---------------- Phase A1: bucket rows by class (blocks 0..63) ----------
    int n0 = blockIdx.x * blockDim.x + t;
    int c_row = -1;
    if (t < Cc) s_cnt[t] = 0;
    __syncthreads();
    if (n0 < Nn) { c_row = y[n0]; atomicAdd(&s_cnt[c_row], 1); }
    __syncthreads();
    if (t < Cc) { s_off[t] = atomicAdd(&g_cnt[t], s_cnt[t]); s_cnt[t] = 0; }
    __syncthreads();
    if (n0 < Nn) {
        int p = atomicAdd(&s_cnt[c_row], 1);
        g_rows[c_row * Nn + s_off[c_row] + p] = n0;
    }

    // ---------------- Phase A2: per-(c,k) precompute (warps 0..159) ----------
    int w = blockIdx.x * (blockDim.x >> 5) + (t >> 5);
    if (w < Cc * Kk) {
        int base = w * Dd + lane * 4;
        float4 m4 = *(const float4*)(mu    + base);
        float4 l4 = *(const float4*)(lower + base);
        float4 u4 = *(const float4*)(upper + base);
        float4 s4 = *(const float4*)(sigma + base);
        float mv[4] = {m4.x, m4.y, m4.z, m4.w};
        float lv[4] = {l4.x, l4.y, l4.z, l4.w};
        float uv[4] = {u4.x, u4.y, u4.z, u4.w};
        float sv[4] = {s4.x, s4.y, s4.z, s4.w};
        float invv[4], m2v[4];
        float prod = 1.0f, slog = 0.0f;
#pragma unroll
        for (int j = 0; j < 4; j++) {
            float scale = EPSf + softplusf(sv[j]);
            float inv   = 1.0f / scale;
            float z = normcdff((uv[j] - mv[j]) * inv) - normcdff((lv[j] - mv[j]) * inv);
            prod *= z;
            slog += logf(scale);
            invv[j] = inv;
            m2v[j]  = mv[j] * inv;
        }
        *(float4*)(g_inv + base) = make_float4(invv[0], invv[1], invv[2], invv[3]);
        *(float4*)(g_m2  + base) = make_float4(m2v[0],  m2v[1],  m2v[2],  m2v[3]);
#pragma unroll
        for (int o = 16; o > 0; o >>= 1) {
            prod *= __shfl_xor_sync(0xffffffffu, prod, o);
            slog += __shfl_xor_sync(0xffffffffu, slog, o);
        }
        if (lane == 0)
            g_pre[w] = -logf(prod + EPSf) - slog;  // -log_norm - sum(log scale)
    }

    // ---------------- grid barrier (all 145 blocks co-resident) --------------
    __syncthreads();
    if (t == 0) {
        __threadfence();
        atomicAdd(&g_bar, 1u);
        while (*(volatile unsigned*)&g_bar < (unsigned)NB) { }
        __threadfence();
    }
    __syncthreads();

    // ---------------- base2[c,k] = -2*base into smem (per block) -------------
    if (t < Cc * Kk) {
        float lg = logits_k[t];
        float m = lg;
#pragma unroll
        for (int o = 8; o > 0; o >>= 1)
            m = fmaxf(m, __shfl_xor_sync(0xffffffffu, m, o, 16));
        float e = expf(lg - m);
        float se = e;
#pragma unroll
        for (int o = 8; o > 0; o >>= 1)
            se += __shfl_xor_sync(0xffffffffu, se, o, 16);
        float log_cat = lg - (m + logf(se));
        float etac = (eta == 0.0f) ? (-2.0f * Dd * LN2f) : 0.0f;
        s_base2[t] = -2.0f * (log_cat + g_pre[t] - 0.5f * Dd * LOG2PIf + etac);
    }
    __syncthreads();

    // ---------------- Phase B: register-resident, 4-row-batched main loop ----
    int c   = w % Cc;
    int s   = w / Cc;
    const int S = (NB * 8) / Cc;         // 116 slices per class
    int cnt = g_cnt[c];

    float4 IV[Kk], MV[Kk];
    {
        const float4* gi = (const float4*)g_inv + (size_t)c * Kk * (Dd / 4) + lane;
        const float4* gm = (const float4*)g_m2  + (size_t)c * Kk * (Dd / 4) + lane;
#pragma unroll
        for (int k = 0; k < Kk; k++) IV[k] = gi[k * (Dd / 4)];
#pragma unroll
        for (int k = 0; k < Kk; k++) MV[k] = gm[k * (Dd / 4)];
    }

    const int* rowlist = g_rows + (size_t)c * Nn;
    int start = (int)(((long)s       * cnt) / S);
    int end   = (int)(((long)(s + 1) * cnt) / S);
    float acc = 0.0f;

    if (eta == 0.0f) {
        if (start < end) {
            // prefetch batch 0
            int    nn[4]; float4 xn[4]; float rn[4];
#pragma unroll
            for (int rr = 0; rr < 4; rr++) {
                int pp = min(start + rr, end - 1);
                nn[rr] = rowlist[pp];
            }
#pragma unroll
            for (int rr = 0; rr < 4; rr++)
                xn[rr] = *(const float4*)(X + (size_t)nn[rr] * Dd + lane * 4);
#pragma unroll
            for (int rr = 0; rr < 4; rr++)
                rn[rr] = (lane < Kk && start + rr < end)
                       ? -0.5f * __ldg(resp + ((size_t)c * Nn + nn[rr]) * Kk + lane)
                       : 0.0f;

            for (int p = start; p < end; p += 4) {
                float4 xc[4]; float rc[4];
#pragma unroll
                for (int rr = 0; rr < 4; rr++) { xc[rr] = xn[rr]; rc[rr] = rn[rr]; }

                int p2 = p + 4;
                if (p2 < end) {
#pragma unroll
                    for (int rr = 0; rr < 4; rr++) {
                        int pp = min(p2 + rr, end - 1);
                        nn[rr] = rowlist[pp];
                    }
#pragma unroll
                    for (int rr = 0; rr < 4; rr++)
                        xn[rr] = *(const float4*)(X + (size_t)nn[rr] * Dd + lane * 4);
#pragma unroll
                    for (int rr = 0; rr < 4; rr++)
                        rn[rr] = (lane < Kk && p2 + rr < end)
                               ? -0.5f * __ldg(resp + ((size_t)c * Nn + nn[rr]) * Kk + lane)
                               : 0.0f;
                }

                float tl[4];
#pragma unroll
                for (int rr = 0; rr < 4; rr++)
                    tl[rr] = (lane < Kk) ? rc[rr] * s_base2[c * Kk + lane] : 0.0f;

#pragma unroll
                for (int k = 0; k < Kk; k++) {
#pragma unroll
                    for (int rr = 0; rr < 4; rr++) {
                        float rh = __shfl_sync(0xffffffffu, rc[rr], k);
                        float z0 = fmaf(xc[rr].x, IV[k].x, -MV[k].x);
                        float z1 = fmaf(xc[rr].y, IV[k].y, -MV[k].y);
                        float z2 = fmaf(xc[rr].z, IV[k].z, -MV[k].z);
                        float z3 = fmaf(xc[rr].w, IV[k].w, -MV[k].w);
                        float sq = fmaf(z0, z0, fmaf(z1, z1, fmaf(z2, z2, z3 * z3)));
                        tl[rr] = fmaf(rh, sq, tl[rr]);   // rh already = -0.5*r
                    }
                }
                acc += (tl[0] + tl[1]) + (tl[2] + tl[3]);
            }
        }
    } else {
        // general path (eta != 0), scalar pipelined version
        for (int pos = start; pos < end; pos++) {
            int n = rowlist[pos];
            float4 xv = *(const float4*)(X + (size_t)n * Dd + lane * 4);
            float respl = (lane < Kk)
                        ? __ldg(resp + ((size_t)c * Nn + n) * Kk + lane) : 0.0f;
            float tl = (lane < Kk) ? respl * (-0.5f * s_base2[c * Kk + lane]) : 0.0f;
            const float4* lp = (const float4*)lower + (size_t)c * Kk * (Dd / 4) + lane;
            const float4* up = (const float4*)upper + (size_t)c * Kk * (Dd / 4) + lane;
#pragma unroll
            for (int k = 0; k < Kk; k++) {
                float4 lo = lp[k * (Dd / 4)];
                float4 uu = up[k * (Dd / 4)];
                float z0 = fmaf(xv.x, IV[k].x, -MV[k].x);
                float z1 = fmaf(xv.y, IV[k].y, -MV[k].y);
                float z2 = fmaf(xv.z, IV[k].z, -MV[k].z);
                float z3 = fmaf(xv.w, IV[k].w, -MV[k].w);
                float sq = fmaf(z0, z0, fmaf(z1, z1, fmaf(z2, z2, z3 * z3)));
                float q  = softplusf(-eta * (xv.x - lo.x)) + softplusf(-eta * (uu.x - xv.x))
                         + softplusf(-eta * (xv.y - lo.y)) + softplusf(-eta * (uu.y - xv.y))
                         + softplusf(-eta * (xv.z - lo.z)) + softplusf(-eta * (uu.z - xv.z))
                         + softplusf(-eta * (xv.w - lo.w)) + softplusf(-eta * (uu.w - xv.w));
                float r  = __shfl_sync(0xffffffffu, respl, k);
                tl -= r * fmaf(0.5f, sq, q);
            }
            acc += tl;
        }
    }

#pragma unroll
    for (int o = 16; o > 0; o >>= 1)
        acc += __shfl_xor_sync(0xffffffffu, acc, o);
    if (lane == 0) atomicAdd(&g_sum[c], acc);

    // ---------------- last block: final reduce + state reset ------------------
    __threadfence();
    __syncthreads();
    if (t == 0) {
        unsigned d = atomicAdd(&g_done, 1u);
        s_last = (d == (unsigned)(NB - 1));
    }
    __syncthreads();
    if (s_last && t < 32) {
        double v = 0.0;
        int cn = 0;
        if (t < Cc) {
            cn = g_cnt[t];
            if (cn > 0) v = (double)g_sum[t] / ((double)cn * (double)Kk);
        }
#pragma unroll
        for (int o = 16; o > 0; o >>= 1)
            v += __shfl_xor_sync(0xffffffffu, v, o);
        if (t == 0) out[0] = (float)(-v);
        // reset state for next graph replay
        if (t < Cc) { g_sum[t] = 0.0f; g_cnt[t] = 0; }
        if (t == 0) { g_bar = 0u; g_done = 0u; }
    }
}

extern "C" void kernel_launch(void* const* d_in, const int* in_sizes, int n_in,
                              void* d_out, int out_size) {
    const float* X      = (const float*)d_in[0];
    const int*   y      = (const int*)  d_in[1];
    const float* resp   = (const float*)d_in[2];
    const float* mu     = (const float*)d_in[3];
    const float* lower  = (const float*)d_in[4];
    const float* upper  = (const float*)d_in[5];
    const float* sigma  = (const float*)d_in[6];
    const float* logits = (const float*)d_in[7];
    const float* eta    = (const float*)d_in[8];
    float* out = (float*)d_out;

    fused_kernel<<<NB, 256>>>(X, y, resp, mu, lower, upper, sigma, logits, eta, out);
}

// round 6
// speedup vs baseline: 1.4557x; 1.0866x over previous
#include <cuda_runtime.h>
#include <math.h>

#define Nn 16384
#define Dd 128
#define Cc 10
#define Kk 16
#define SLICES 29
#define NB (SLICES * Cc)          // 290 blocks; 2/SM guaranteed -> co-resident
#define EPSf 1.1920928955078125e-7f
#define LOG2PIf 1.8378770664093453f
#define LN2f 0.6931471805599453f

// static scratch (no allocation); all-zero initial state, restored at end of
// every run by the winner block so graph replays are self-contained.
__device__ float    g_inv[Cc * Kk * Dd];
__device__ float    g_m2 [Cc * Kk * Dd];
__device__ float    g_pre[Cc * Kk];
__device__ float    g_sum[Cc];
__device__ int      g_cnt[Cc];
__device__ int      g_rows[Cc * Nn];
__device__ unsigned g_bar;
__device__ unsigned g_done;

__device__ __forceinline__ float softplusf(float x) {
    return fmaxf(x, 0.0f) + log1pf(expf(-fabsf(x)));
}

__global__ void __launch_bounds__(256, 2)
fused_kernel(const float* __restrict__ X, const int* __restrict__ y,
             const float* __restrict__ resp,
             const float* __restrict__ mu,
             const float* __restrict__ lower, const float* __restrict__ upper,
             const float* __restrict__ sigma,
             const float* __restrict__ logits_k,
             const float* __restrict__ eta_p,
             float* __restrict__ out) {
    __shared__ float4 s_iv[Kk * 32];     // 8 KB: this block's class inv (k-major, lane float4)
    __shared__ float4 s_mv[Kk * 32];     // 8 KB: this block's class m2
    __shared__ int    s_cnt[Cc];
    __shared__ int    s_off[Cc];
    __shared__ float  s_b2[Kk];          // -2*base for this block's class
    __shared__ float  s_wsum[8];
    __shared__ bool   s_last;

    int t    = threadIdx.x;
    int lane = t & 31;
    int w8   = t >> 5;
    float eta = *eta_p;

    // ---------------- Phase A1: bucket rows by class (blocks 0..63) ----------
    int n0 = blockIdx.x * blockDim.x + t;
    int c_row = -1;
    if (t < Cc) s_cnt[t] = 0;
    __syncthreads();
    if (n0 < Nn) { c_row = y[n0]; atomicAdd(&s_cnt[c_row], 1); }
    __syncthreads();
    if (t < Cc) { s_off[t] = atomicAdd(&g_cnt[t], s_cnt[t]); s_cnt[t] = 0; }
    __syncthreads();
    if (n0 < Nn) {
        int p = atomicAdd(&s_cnt[c_row], 1);
        g_rows[c_row * Nn + s_off[c_row] + p] = n0;
    }

    // ---------------- Phase A2: per-(c,k) precompute (warps 0..159) ----------
    int w = blockIdx.x * 8 + w8;
    if (w < Cc * Kk) {
        int base = w * Dd + lane * 4;
        float4 m4 = *(const float4*)(mu    + base);
        float4 l4 = *(const float4*)(lower + base);
        float4 u4 = *(const float4*)(upper + base);
        float4 s4 = *(const float4*)(sigma + base);
        float mv[4] = {m4.x, m4.y, m4.z, m4.w};
        float lv[4] = {l4.x, l4.y, l4.z, l4.w};
        float uv[4] = {u4.x, u4.y, u4.z, u4.w};
        float sv[4] = {s4.x, s4.y, s4.z, s4.w};
        float invv[4], m2v[4];
        float prod = 1.0f, slog = 0.0f;
#pragma unroll
        for (int j = 0; j < 4; j++) {
            float scale = EPSf + softplusf(sv[j]);
            float inv   = 1.0f / scale;
            float z = normcdff((uv[j] - mv[j]) * inv) - normcdff((lv[j] - mv[j]) * inv);
            prod *= z;
            slog += logf(scale);
            invv[j] = inv;
            m2v[j]  = mv[j] * inv;
        }
        *(float4*)(g_inv + base) = make_float4(invv[0], invv[1], invv[2], invv[3]);
        *(float4*)(g_m2  + base) = make_float4(m2v[0],  m2v[1],  m2v[2],  m2v[3]);
#pragma unroll
        for (int o = 16; o > 0; o >>= 1) {
            prod *= __shfl_xor_sync(0xffffffffu, prod, o);
            slog += __shfl_xor_sync(0xffffffffu, slog, o);
        }
        if (lane == 0)
            g_pre[w] = -logf(prod + EPSf) - slog;  // -log_norm - sum(log scale)
    }

    // ---------------- grid barrier (290 blocks, 2/SM guaranteed) -------------
    __syncthreads();
    if (t == 0) {
        __threadfence();
        atomicAdd(&g_bar, 1u);
        while (*(volatile unsigned*)&g_bar < (unsigned)NB) { __nanosleep(32); }
        __threadfence();
    }
    __syncthreads();

    // ---------------- this block's class + smem weights ----------------------
    int c     = blockIdx.x % Cc;
    int slice = blockIdx.x / Cc;

    // cooperative load of 16 KB weights (L2-broadcast across blocks)
    {
        const float4* gi = (const float4*)g_inv + (size_t)c * (Kk * 32);
        const float4* gm = (const float4*)g_m2  + (size_t)c * (Kk * 32);
        for (int i = t; i < Kk * 32; i += 256) {
            s_iv[i] = gi[i];
            s_mv[i] = gm[i];
        }
    }

    // base2[k] = -2*base for class c (warp 0)
    if (t < 32) {
        int kk = t & 15;
        float lg = logits_k[c * Kk + kk];
        float m = lg;
#pragma unroll
        for (int o = 8; o > 0; o >>= 1)
            m = fmaxf(m, __shfl_xor_sync(0xffffffffu, m, o, 16));
        float e = expf(lg - m);
        float se = e;
#pragma unroll
        for (int o = 8; o > 0; o >>= 1)
            se += __shfl_xor_sync(0xffffffffu, se, o, 16);
        float log_cat = lg - (m + logf(se));
        float etac = (eta == 0.0f) ? (-2.0f * Dd * LN2f) : 0.0f;
        if (t < Kk)
            s_b2[t] = -2.0f * (log_cat + g_pre[c * Kk + kk] - 0.5f * Dd * LOG2PIf + etac);
    }
    __syncthreads();

    // ---------------- Phase B: smem-weight main loop, 4 rows/iter ------------
    int cnt   = g_cnt[c];
    int start = (int)(((long)slice       * cnt) / SLICES);
    int end   = (int)(((long)(slice + 1) * cnt) / SLICES);
    // warp sub-range within [start,end)
    int len = end - start;
    int ws  = start + (len * w8)     / 8;
    int we  = start + (len * (w8+1)) / 8;

    const int* rowlist = g_rows + (size_t)c * Nn;
    float acc = 0.0f;

    if (eta == 0.0f) {
        for (int p = ws; p < we; p += 4) {
            int nn[4];
#pragma unroll
            for (int rr = 0; rr < 4; rr++) {
                int pp = min(p + rr, we - 1);
                nn[rr] = rowlist[pp];
            }
            float4 xc[4];
#pragma unroll
            for (int rr = 0; rr < 4; rr++)
                xc[rr] = *(const float4*)(X + (size_t)nn[rr] * Dd + lane * 4);
            float rc[4];
#pragma unroll
            for (int rr = 0; rr < 4; rr++)
                rc[rr] = (lane < Kk && p + rr < we)
                       ? -0.5f * __ldg(resp + ((size_t)c * Nn + nn[rr]) * Kk + lane)
                       : 0.0f;

            float tl[4];
#pragma unroll
            for (int rr = 0; rr < 4; rr++)
                tl[rr] = (lane < Kk) ? rc[rr] * s_b2[lane] : 0.0f;

#pragma unroll
            for (int k = 0; k < Kk; k++) {
                float4 iv = s_iv[k * 32 + lane];
                float4 mv = s_mv[k * 32 + lane];
#pragma unroll
                for (int rr = 0; rr < 4; rr++) {
                    float rh = __shfl_sync(0xffffffffu, rc[rr], k);
                    float z0 = fmaf(xc[rr].x, iv.x, -mv.x);
                    float z1 = fmaf(xc[rr].y, iv.y, -mv.y);
                    float z2 = fmaf(xc[rr].z, iv.z, -mv.z);
                    float z3 = fmaf(xc[rr].w, iv.w, -mv.w);
                    float sq = fmaf(z0, z0, fmaf(z1, z1, fmaf(z2, z2, z3 * z3)));
                    tl[rr] = fmaf(rh, sq, tl[rr]);   // rh already = -0.5*r
                }
            }
            acc += (tl[0] + tl[1]) + (tl[2] + tl[3]);
        }
    } else {
        // general path (eta != 0)
        for (int pos = ws; pos < we; pos++) {
            int n = rowlist[pos];
            float4 xv = *(const float4*)(X + (size_t)n * Dd + lane * 4);
            float respl = (lane < Kk)
                        ? __ldg(resp + ((size_t)c * Nn + n) * Kk + lane) : 0.0f;
            float tl = (lane < Kk) ? respl * (-0.5f * s_b2[lane]) : 0.0f;
            const float4* lp = (const float4*)lower + (size_t)c * Kk * 32 + lane;
            const float4* up = (const float4*)upper + (size_t)c * Kk * 32 + lane;
#pragma unroll
            for (int k = 0; k < Kk; k++) {
                float4 iv = s_iv[k * 32 + lane];
                float4 mv = s_mv[k * 32 + lane];
                float4 lo = lp[k * 32];
                float4 uu = up[k * 32];
                float z0 = fmaf(xv.x, iv.x, -mv.x);
                float z1 = fmaf(xv.y, iv.y, -mv.y);
                float z2 = fmaf(xv.z, iv.z, -mv.z);
                float z3 = fmaf(xv.w, iv.w, -mv.w);
                float sq = fmaf(z0, z0, fmaf(z1, z1, fmaf(z2, z2, z3 * z3)));
                float q  = softplusf(-eta * (xv.x - lo.x)) + softplusf(-eta * (uu.x - xv.x))
                         + softplusf(-eta * (xv.y - lo.y)) + softplusf(-eta * (uu.y - xv.y))
                         + softplusf(-eta * (xv.z - lo.z)) + softplusf(-eta * (uu.z - xv.z))
                         + softplusf(-eta * (xv.w - lo.w)) + softplusf(-eta * (uu.w - xv.w));
                float r  = __shfl_sync(0xffffffffu, respl, k);
                tl -= r * fmaf(0.5f, sq, q);
            }
            acc += tl;
        }
    }

    // block reduce (all warps same class) -> one atomic per block
#pragma unroll
    for (int o = 16; o > 0; o >>= 1)
        acc += __shfl_xor_sync(0xffffffffu, acc, o);
    if (lane == 0) s_wsum[w8] = acc;
    __syncthreads();
    if (t == 0) {
        float b = ((s_wsum[0] + s_wsum[1]) + (s_wsum[2] + s_wsum[3]))
                + ((s_wsum[4] + s_wsum[5]) + (s_wsum[6] + s_wsum[7]));
        atomicAdd(&g_sum[c], b);
    }

    // ---------------- last block: final reduce + state reset ------------------
    __threadfence();
    __syncthreads();
    if (t == 0) {
        unsigned d = atomicAdd(&g_done, 1u);
        s_last = (d == (unsigned)(NB - 1));
    }
    __syncthreads();
    if (s_last && t < 32) {
        double v = 0.0;
        if (t < Cc) {
            int cn = g_cnt[t];
            if (cn > 0) v = (double)g_sum[t] / ((double)cn * (double)Kk);
        }
#pragma unroll
        for (int o = 16; o > 0; o >>= 1)
            v += __shfl_xor_sync(0xffffffffu, v, o);
        if (t == 0) out[0] = (float)(-v);
        // reset state for next graph replay
        if (t < Cc) { g_sum[t] = 0.0f; g_cnt[t] = 0; }
        if (t == 0) { g_bar = 0u; g_done = 0u; }
    }
}

extern "C" void kernel_launch(void* const* d_in, const int* in_sizes, int n_in,
                              void* d_out, int out_size) {
    const float* X      = (const float*)d_in[0];
    const int*   y      = (const int*)  d_in[1];
    const float* resp   = (const float*)d_in[2];
    const float* mu     = (const float*)d_in[3];
    const float* lower  = (const float*)d_in[4];
    const float* upper  = (const float*)d_in[5];
    const float* sigma  = (const float*)d_in[6];
    const float* logits = (const float*)d_in[7];
    const float* eta    = (const float*)d_in[8];
    float* out = (float*)d_out;

    fused_kernel<<<NB, 256>>>(X, y, resp, mu, lower, upper, sigma, logits, eta, out);
}

// round 8
// speedup vs baseline: 1.5068x; 1.0351x over previous
#include <cuda_runtime.h>
#include <math.h>

#define Nn 16384
#define Dd 128
#define Cc 10
#define Kk 16
#define SLICES 29
#define NB (SLICES * Cc)          // 290 blocks; 2/SM guaranteed -> co-resident
#define EPSf 1.1920928955078125e-7f
#define LOG2PIf 1.8378770664093453f
#define LN2f 0.6931471805599453f

// static scratch (no allocation); all-zero initial state, restored at end of
// every run by the winner block so graph replays are self-contained.
__device__ float    g_inv[Cc * Kk * Dd];
__device__ float    g_m2 [Cc * Kk * Dd];
__device__ float    g_pre[Cc * Kk];
__device__ float    g_sum[Cc];
__device__ int      g_cnt[Cc];
__device__ int      g_rows[Cc * Nn];
__device__ unsigned g_bar;
__device__ unsigned g_done;

typedef unsigned long long u64;

__device__ __forceinline__ float softplusf(float x) {
    return fmaxf(x, 0.0f) + log1pf(expf(-fabsf(x)));
}

// packed f32x2 helpers (sm_100a): a u64 carries two packed floats (lo,hi).
__device__ __forceinline__ u64 fma2(u64 a, u64 b, u64 c) {
    u64 r; asm("fma.rn.f32x2 %0,%1,%2,%3;" : "=l"(r) : "l"(a), "l"(b), "l"(c)); return r;
}
__device__ __forceinline__ u64 mul2(u64 a, u64 b) {
    u64 r; asm("mul.rn.f32x2 %0,%1,%2;" : "=l"(r) : "l"(a), "l"(b)); return r;
}
__device__ __forceinline__ void upk2(u64 d, float& lo, float& hi) {
    asm("mov.b64 {%0,%1},%2;" : "=f"(lo), "=f"(hi) : "l"(d));
}

__global__ void __launch_bounds__(256, 2)
fused_kernel(const float* __restrict__ X, const int* __restrict__ y,
             const float* __restrict__ resp,
             const float* __restrict__ mu,
             const float* __restrict__ lower, const float* __restrict__ upper,
             const float* __restrict__ sigma,
             const float* __restrict__ logits_k,
             const float* __restrict__ eta_p,
             float* __restrict__ out) {
    __shared__ float4 s_iv[Kk * 32];     // 8 KB: class inv  (k-major, lane float4)
    __shared__ float4 s_nm[Kk * 32];     // 8 KB: class -m2  (negated!)
    __shared__ int    s_cnt[Cc];
    __shared__ int    s_off[Cc];
    __shared__ float  s_b2[Kk];          // -2*base for this block's class
    __shared__ float  s_wsum[8];
    __shared__ bool   s_last;

    int t    = threadIdx.x;
    int lane = t & 31;
    int w8   = t >> 5;
    float eta = *eta_p;

    // ---------------- Phase A1: bucket rows (ALL blocks, ~57 rows each) ------
    int bs = (int)(((long)blockIdx.x       * Nn) / NB);
    int be = (int)(((long)(blockIdx.x + 1) * Nn) / NB);
    int n0 = bs + t;
    int c_row = -1;
    if (t < Cc) s_cnt[t] = 0;
    __syncthreads();
    if (n0 < be) { c_row = y[n0]; atomicAdd(&s_cnt[c_row], 1); }
    __syncthreads();
    if (t < Cc) { s_off[t] = atomicAdd(&g_cnt[t], s_cnt[t]); s_cnt[t] = 0; }
    __syncthreads();
    if (n0 < be) {
        int p = atomicAdd(&s_cnt[c_row], 1);
        g_rows[c_row * Nn + s_off[c_row] + p] = n0;
    }

    // ---------------- Phase A2: per-(c,k) precompute (warps 0..159) ----------
    int w = blockIdx.x * 8 + w8;
    if (w < Cc * Kk) {
        int base = w * Dd + lane * 4;
        float4 m4 = *(const float4*)(mu    + base);
        float4 l4 = *(const float4*)(lower + base);
        float4 u4 = *(const float4*)(upper + base);
        float4 s4 = *(const float4*)(sigma + base);
        float mv[4] = {m4.x, m4.y, m4.z, m4.w};
        float lv[4] = {l4.x, l4.y, l4.z, l4.w};
        float uv[4] = {u4.x, u4.y, u4.z, u4.w};
        float sv[4] = {s4.x, s4.y, s4.z, s4.w};
        float invv[4], m2v[4];
        float prod = 1.0f, slog = 0.0f;
#pragma unroll
        for (int j = 0; j < 4; j++) {
            float scale = EPSf + softplusf(sv[j]);
            float inv   = 1.0f / scale;
            float z = normcdff((uv[j] - mv[j]) * inv) - normcdff((lv[j] - mv[j]) * inv);
            prod *= z;
            slog += logf(scale);
            invv[j] = inv;
            m2v[j]  = mv[j] * inv;
        }
        *(float4*)(g_inv + base) = make_float4(invv[0], invv[1], invv[2], invv[3]);
        *(float4*)(g_m2  + base) = make_float4(m2v[0],  m2v[1],  m2v[2],  m2v[3]);
#pragma unroll
        for (int o = 16; o > 0; o >>= 1) {
            prod *= __shfl_xor_sync(0xffffffffu, prod, o);
            slog += __shfl_xor_sync(0xffffffffu, slog, o);
        }
        if (lane == 0)
            g_pre[w] = -logf(prod + EPSf) - slog;  // -log_norm - sum(log scale)
    }

    // ---------------- grid barrier (290 blocks, 2/SM guaranteed) -------------
    __syncthreads();
    if (t == 0) {
        __threadfence();
        atomicAdd(&g_bar, 1u);
        while (*(volatile unsigned*)&g_bar < (unsigned)NB) { __nanosleep(32); }
        __threadfence();
    }
    __syncthreads();

    // ---------------- this block's class + smem weights ----------------------
    int c     = blockIdx.x % Cc;
    int slice = blockIdx.x / Cc;

    {   // cooperative load (negate m2 on the way in)
        const float4* gi = (const float4*)g_inv + (size_t)c * (Kk * 32);
        const float4* gm = (const float4*)g_m2  + (size_t)c * (Kk * 32);
        for (int i = t; i < Kk * 32; i += 256) {
            s_iv[i] = gi[i];
            float4 m = gm[i];
            s_nm[i] = make_float4(-m.x, -m.y, -m.z, -m.w);
        }
    }

    // base2[k] = -2*base for class c (warp 0)
    if (t < 32) {
        int kk = t & 15;
        float lg = logits_k[c * Kk + kk];
        float m = lg;
#pragma unroll
        for (int o = 8; o > 0; o >>= 1)
            m = fmaxf(m, __shfl_xor_sync(0xffffffffu, m, o, 16));
        float e = expf(lg - m);
        float se = e;
#pragma unroll
        for (int o = 8; o > 0; o >>= 1)
            se += __shfl_xor_sync(0xffffffffu, se, o, 16);
        float log_cat = lg - (m + logf(se));
        float etac = (eta == 0.0f) ? (-2.0f * Dd * LN2f) : 0.0f;
        if (t < Kk)
            s_b2[t] = -2.0f * (log_cat + g_pre[c * Kk + kk] - 0.5f * Dd * LOG2PIf + etac);
    }
    __syncthreads();

    // ---------------- Phase B: pipelined smem-weight main loop ---------------
    int cnt   = g_cnt[c];
    int start = (int)(((long)slice       * cnt) / SLICES);
    int end   = (int)(((long)(slice + 1) * cnt) / SLICES);
    int len = end - start;
    int ws  = start + (len * w8)     / 8;
    int we  = start + (len * (w8+1)) / 8;

    const int* rowlist = g_rows + (size_t)c * Nn;
    const ulonglong2* s_ivd = (const ulonglong2*)s_iv;
    const ulonglong2* s_nmd = (const ulonglong2*)s_nm;
    float acc = 0.0f;

    if (eta == 0.0f) {
        if (ws < we) {
            // prefetch batch 0 (X rows aliased as ulonglong2 = two f32x2 operands)
            int nn[4]; ulonglong2 xn[4]; float rn[4];
#pragma unroll
            for (int rr = 0; rr < 4; rr++) nn[rr] = rowlist[min(ws + rr, we - 1)];
#pragma unroll
            for (int rr = 0; rr < 4; rr++)
                xn[rr] = *(const ulonglong2*)(X + (size_t)nn[rr] * Dd + lane * 4);
#pragma unroll
            for (int rr = 0; rr < 4; rr++)
                rn[rr] = (lane < Kk && ws + rr < we)
                       ? -0.5f * __ldg(resp + ((size_t)c * Nn + nn[rr]) * Kk + lane)
                       : 0.0f;

            for (int p = ws; p < we; p += 4) {
                ulonglong2 xc[4]; float rc[4];
#pragma unroll
                for (int rr = 0; rr < 4; rr++) { xc[rr] = xn[rr]; rc[rr] = rn[rr]; }

                int p2 = p + 4;
                if (p2 < we) {
#pragma unroll
                    for (int rr = 0; rr < 4; rr++) nn[rr] = rowlist[min(p2 + rr, we - 1)];
#pragma unroll
                    for (int rr = 0; rr < 4; rr++)
                        xn[rr] = *(const ulonglong2*)(X + (size_t)nn[rr] * Dd + lane * 4);
#pragma unroll
                    for (int rr = 0; rr < 4; rr++)
                        rn[rr] = (lane < Kk && p2 + rr < we)
                               ? -0.5f * __ldg(resp + ((size_t)c * Nn + nn[rr]) * Kk + lane)
                               : 0.0f;
                }

                float tl[4];
#pragma unroll
                for (int rr = 0; rr < 4; rr++)
                    tl[rr] = (lane < Kk) ? rc[rr] * s_b2[lane] : 0.0f;

#pragma unroll
                for (int k = 0; k < Kk; k++) {
                    ulonglong2 iv = s_ivd[k * 32 + lane];
                    ulonglong2 nm = s_nmd[k * 32 + lane];
#pragma unroll
                    for (int rr = 0; rr < 4; rr++) {
                        float rh = __shfl_sync(0xffffffffu, rc[rr], k);
                        u64 z01 = fma2(xc[rr].x, iv.x, nm.x);
                        u64 z23 = fma2(xc[rr].y, iv.y, nm.y);
                        u64 sp  = fma2(z01, z01, mul2(z23, z23));
                        float slo, shi; upk2(sp, slo, shi);
                        tl[rr] = fmaf(rh, slo + shi, tl[rr]);   // rh = -0.5*r
                    }
                }
                acc += (tl[0] + tl[1]) + (tl[2] + tl[3]);
            }
        }
    } else {
        // general path (eta != 0); s_nm holds NEGATED m2
        for (int pos = ws; pos < we; pos++) {
            int n = rowlist[pos];
            float4 xv = *(const float4*)(X + (size_t)n * Dd + lane * 4);
            float respl = (lane < Kk)
                        ? __ldg(resp + ((size_t)c * Nn + n) * Kk + lane) : 0.0f;
            float tl = (lane < Kk) ? respl * (-0.5f * s_b2[lane]) : 0.0f;
            const float4* lp = (const float4*)lower + (size_t)c * Kk * 32 + lane;
            const float4* up = (const float4*)upper + (size_t)c * Kk * 32 + lane;
#pragma unroll
            for (int k = 0; k < Kk; k++) {
                float4 iv = s_iv[k * 32 + lane];
                float4 nm = s_nm[k * 32 + lane];
                float4 lo = lp[k * 32];
                float4 uu = up[k * 32];
                float z0 = fmaf(xv.x, iv.x, nm.x);
                float z1 = fmaf(xv.y, iv.y, nm.y);
                float z2 = fmaf(xv.z, iv.z, nm.z);
                float z3 = fmaf(xv.w, iv.w, nm.w);
                float sq = fmaf(z0, z0, fmaf(z1, z1, fmaf(z2, z2, z3 * z3)));
                float q  = softplusf(-eta * (xv.x - lo.x)) + softplusf(-eta * (uu.x - xv.x))
                         + softplusf(-eta * (xv.y - lo.y)) + softplusf(-eta * (uu.y - xv.y))
                         + softplusf(-eta * (xv.z - lo.z)) + softplusf(-eta * (uu.z - xv.z))
                         + softplusf(-eta * (xv.w - lo.w)) + softplusf(-eta * (uu.w - xv.w));
                float r  = __shfl_sync(0xffffffffu, respl, k);
                tl -= r * fmaf(0.5f, sq, q);
            }
            acc += tl;
        }
    }

    // block reduce (all warps same class) -> one atomic per block
#pragma unroll
    for (int o = 16; o > 0; o >>= 1)
        acc += __shfl_xor_sync(0xffffffffu, acc, o);
    if (lane == 0) s_wsum[w8] = acc;
    __syncthreads();
    if (t == 0) {
        float b = ((s_wsum[0] + s_wsum[1]) + (s_wsum[2] + s_wsum[3]))
                + ((s_wsum[4] + s_wsum[5]) + (s_wsum[6] + s_wsum[7]));
        atomicAdd(&g_sum[c], b);
    }

    // ---------------- last block: final reduce + state reset ------------------
    __threadfence();
    __syncthreads();
    if (t == 0) {
        unsigned d = atomicAdd(&g_done, 1u);
        s_last = (d == (unsigned)(NB - 1));
    }
    __syncthreads();
    if (s_last && t < 32) {
        double v = 0.0;
        if (t < Cc) {
            int cn = g_cnt[t];
            if (cn > 0) v = (double)g_sum[t] / ((double)cn * (double)Kk);
        }
#pragma unroll
        for (int o = 16; o > 0; o >>= 1)
            v += __shfl_xor_sync(0xffffffffu, v, o);
        if (t == 0) out[0] = (float)(-v);
        // reset state for next graph replay
        if (t < Cc) { g_sum[t] = 0.0f; g_cnt[t] = 0; }
        if (t == 0) { g_bar = 0u; g_done = 0u; }
    }
}

extern "C" void kernel_launch(void* const* d_in, const int* in_sizes, int n_in,
                              void* d_out, int out_size) {
    const float* X      = (const float*)d_in[0];
    const int*   y      = (const int*)  d_in[1];
    const float* resp   = (const float*)d_in[2];
    const float* mu     = (const float*)d_in[3];
    const float* lower  = (const float*)d_in[4];
    const float* upper  = (const float*)d_in[5];
    const float* sigma  = (const float*)d_in[6];
    const float* logits = (const float*)d_in[7];
    const float* eta    = (const float*)d_in[8];
    float* out = (float*)d_out;

    fused_kernel<<<NB, 256>>>(X, y, resp, mu, lower, upper, sigma, logits, eta, out);
}